// round 16
// baseline (speedup 1.0000x reference)
#include <cuda_runtime.h>
#include <cuda_bf16.h>
#include <cstdint>

// Problem constants
#define Bn   64
#define Cc   768
#define HW   676          // 26*26
#define Mm   32
#define NCLS 200
#define MC   (Mm*Cc)      // 24576
#define OFF_P   0
#define OFF_FM  (Bn*NCLS)                  // 12800
#define OFF_ATT (OFF_FM + Bn*MC)           // 12800 + 1572864

// Scratch (device-code use only; never passed from host).
__device__ float g_ss[Bn];             // per-batch sum of f^2 (atomic)
__device__ float g_scale[Bn];          // 1/max(||f||,eps)  (written by k_norm path)

// ===========================================================================
// Baseline-ISA tensor helpers (ldmatrix + mma.sync assemble for plain sm_103;
// tcgen05 does NOT — harness assembles a non-'a' target).
// ===========================================================================
__device__ __forceinline__ uint32_t smem_u32(const void* p) {
    uint32_t r;
    asm("{ .reg .u64 t; cvta.to.shared.u64 t, %1; cvt.u32.u64 %0, t; }"
        : "=r"(r) : "l"(p));
    return r;
}
#define SWZ128(o)  ((o) ^ (((o) >> 3) & 0x70))

__device__ __forceinline__ void ldsm_x4(uint32_t addr, uint32_t r[4]) {
    asm volatile("ldmatrix.sync.aligned.m8n8.x4.shared.b16 {%0,%1,%2,%3}, [%4];"
                 : "=r"(r[0]), "=r"(r[1]), "=r"(r[2]), "=r"(r[3]) : "r"(addr));
}
__device__ __forceinline__ void ldsm_x4_t(uint32_t addr, uint32_t r[4]) {
    asm volatile("ldmatrix.sync.aligned.m8n8.x4.trans.shared.b16 {%0,%1,%2,%3}, [%4];"
                 : "=r"(r[0]), "=r"(r[1]), "=r"(r[2]), "=r"(r[3]) : "r"(addr));
}
__device__ __forceinline__ void mma_bf16(float* c, const uint32_t a[4],
                                         uint32_t b0, uint32_t b1) {
    asm volatile(
        "mma.sync.aligned.m16n8k16.row.col.f32.bf16.bf16.f32 "
        "{%0,%1,%2,%3}, {%4,%5,%6,%7}, {%8,%9}, {%0,%1,%2,%3};"
        : "+f"(c[0]), "+f"(c[1]), "+f"(c[2]), "+f"(c[3])
        : "r"(a[0]), "r"(a[1]), "r"(a[2]), "r"(a[3]), "r"(b0), "r"(b1));
}

// hi/lo bf16 split of a float pair (exact residual; minimal issue count)
__device__ __forceinline__ void split_pack(float x, float y,
                                           uint32_t& hi, uint32_t& lo) {
    __nv_bfloat162 h2 = __floats2bfloat162_rn(x, y);    // x -> low half
    uint32_t h = *(uint32_t*)&h2;
    float hx = __uint_as_float(h << 16);
    float hy = __uint_as_float(h & 0xFFFF0000u);
    __nv_bfloat162 l2 = __floats2bfloat162_rn(x - hx, y - hy);
    hi = h;
    lo = *(uint32_t*)&l2;
}

// ---------------------------------------------------------------------------
// Kernel A (mma.sync, double-buffered): att = relu(W @ X + bias)
// Per CTA (hw-tile 128, batch b): D[32m x 128hw], K = c in 12 chunks of 64.
// (mma order = R13 grouped form — best measured; R15 reorder was neutral-
//  negative and reverted.)
// ---------------------------------------------------------------------------
#define KCH      64
#define NKCH     12
#define PXB      272                    // X row pitch bytes (136 bf16)
#define X_HI_OFF 0                      // 64*272 = 17408
#define X_LO_OFF 17408
#define W_HI_OFF 34816                  // 34*1024 (SW128 region 1024-aligned)
#define W_LO_OFF 38912
#define ATT_BUF  43008                  // 42*1024
#define ATT_SMEM_DYN (2 * ATT_BUF + 1024)

__global__ __launch_bounds__(256, 2) void k_att_mma(
    const float* __restrict__ fmap, const float* __restrict__ attw,
    const float* __restrict__ attb, float* __restrict__ out_att)
{
    extern __shared__ char dyn_smem[];
    const int b   = blockIdx.y;
    const int hwt = blockIdx.x * 128;
    const int t   = threadIdx.x;
    const int w   = t >> 5, lane = t & 31;

    if (blockIdx.x == 0 && t == 0) g_ss[b] = 0.f;   // pre-zero for pool atomics

    uint32_t raw = smem_u32(dyn_smem);
    uint32_t abase = (raw + 1023u) & ~1023u;
    char* sbuf = dyn_smem + (abase - raw);

    const float* X = fmap + (size_t)b * Cc * HW;

    float acc[2][2][4];
#pragma unroll
    for (int mt = 0; mt < 2; ++mt)
#pragma unroll
        for (int nt = 0; nt < 2; ++nt)
#pragma unroll
            for (int j = 0; j < 4; ++j) acc[mt][nt][j] = 0.f;

    const int r8 = lane & 7;
    const int aRowIn = ((lane >> 3) & 1) * 8 + r8;
    const int aColB  = ((lane >> 4) & 1) * 16;
    const int bKrow  = lane & 15;
    const int bNcol  = w * 16 + ((lane >> 4) & 1) * 8;

    float4 xv[8], wv[2];
    const int xrow[8] = { (t) >> 5, (t + 256) >> 5, (t + 512) >> 5, (t + 768) >> 5,
                          (t + 1024) >> 5, (t + 1280) >> 5, (t + 1536) >> 5, (t + 1792) >> 5 };
    const int xqc  = t & 31;
    const int xhw  = hwt + xqc * 4;
    const bool xok = xhw < HW;          // HW%4==0 -> whole quad in range
    const int wrow[2] = { t >> 4, (t + 256) >> 4 };
    const int wqc  = t & 15;

#define ATT_LOAD(c0_)                                                         \
    do {                                                                      \
        _Pragma("unroll")                                                     \
        for (int i = 0; i < 8; ++i)                                           \
            xv[i] = xok ? *(const float4*)(X + (size_t)((c0_) + xrow[i]) * HW + xhw) \
                        : make_float4(0.f, 0.f, 0.f, 0.f);                    \
        _Pragma("unroll")                                                     \
        for (int i = 0; i < 2; ++i)                                           \
            wv[i] = *(const float4*)(attw + (size_t)wrow[i] * Cc + (c0_) + wqc * 4); \
    } while (0)

#define ATT_STORE(dst_)                                                       \
    do {                                                                      \
        char* db_ = (dst_);                                                   \
        _Pragma("unroll")                                                     \
        for (int i = 0; i < 8; ++i) {                                         \
            uint32_t h01, l01, h23, l23;                                      \
            split_pack(xv[i].x, xv[i].y, h01, l01);                           \
            split_pack(xv[i].z, xv[i].w, h23, l23);                           \
            uint32_t off = (uint32_t)(xrow[i] * PXB + xqc * 8);               \
            *(uint2*)(db_ + X_HI_OFF + off) = make_uint2(h01, h23);           \
            *(uint2*)(db_ + X_LO_OFF + off) = make_uint2(l01, l23);           \
        }                                                                     \
        _Pragma("unroll")                                                     \
        for (int i = 0; i < 2; ++i) {                                         \
            uint32_t h01, l01, h23, l23;                                      \
            split_pack(wv[i].x, wv[i].y, h01, l01);                           \
            split_pack(wv[i].z, wv[i].w, h23, l23);                           \
            uint32_t off = SWZ128((uint32_t)(wrow[i] * 128 + wqc * 8));       \
            *(uint2*)(db_ + W_HI_OFF + off) = make_uint2(h01, h23);           \
            *(uint2*)(db_ + W_LO_OFF + off) = make_uint2(l01, l23);           \
        }                                                                     \
    } while (0)

    ATT_LOAD(0);
    ATT_STORE(sbuf);
    __syncthreads();

    for (int ch = 0; ch < NKCH; ++ch) {
        const uint32_t abuf = abase + (uint32_t)(ch & 1) * ATT_BUF;
        if (ch + 1 < NKCH) ATT_LOAD((ch + 1) * KCH);   // LDG in flight over mma

#pragma unroll
        for (int ks = 0; ks < 4; ++ks) {
            uint32_t ah[2][4], al[2][4];
#pragma unroll
            for (int mt = 0; mt < 2; ++mt) {
                uint32_t aOff = SWZ128((uint32_t)((mt * 16 + aRowIn) * 128 +
                                                  ks * 32 + aColB));
                ldsm_x4(abuf + W_HI_OFF + aOff, ah[mt]);
                ldsm_x4(abuf + W_LO_OFF + aOff, al[mt]);
            }
            uint32_t bOff = (uint32_t)((ks * 16 + bKrow) * PXB + bNcol * 2);
            uint32_t bh[4], bl[4];
            ldsm_x4_t(abuf + X_HI_OFF + bOff, bh);
            ldsm_x4_t(abuf + X_LO_OFF + bOff, bl);
#pragma unroll
            for (int mt = 0; mt < 2; ++mt)
#pragma unroll
                for (int nt = 0; nt < 2; ++nt) {
                    mma_bf16(acc[mt][nt], ah[mt], bh[2 * nt], bh[2 * nt + 1]);
                    mma_bf16(acc[mt][nt], ah[mt], bl[2 * nt], bl[2 * nt + 1]);
                    mma_bf16(acc[mt][nt], al[mt], bh[2 * nt], bh[2 * nt + 1]);
                }
        }

        if (ch + 1 < NKCH) ATT_STORE(sbuf + ((ch + 1) & 1) * ATT_BUF);
        __syncthreads();
    }

    float* ob = out_att + (size_t)b * Mm * HW;
#pragma unroll
    for (int mt = 0; mt < 2; ++mt) {
        const int m  = mt * 16 + (lane >> 2);
        const float bs0 = __ldg(&attb[m]);
        const float bs8 = __ldg(&attb[m + 8]);
#pragma unroll
        for (int nt = 0; nt < 2; ++nt) {
            int hwc = hwt + w * 16 + nt * 8 + 2 * (lane & 3);
            if (hwc + 1 < HW) {
                ob[(size_t)m * HW + hwc]           = fmaxf(acc[mt][nt][0] + bs0, 0.f);
                ob[(size_t)m * HW + hwc + 1]       = fmaxf(acc[mt][nt][1] + bs0, 0.f);
                ob[(size_t)(m + 8) * HW + hwc]     = fmaxf(acc[mt][nt][2] + bs8, 0.f);
                ob[(size_t)(m + 8) * HW + hwc + 1] = fmaxf(acc[mt][nt][3] + bs8, 0.f);
            }
        }
    }
#undef ATT_LOAD
#undef ATT_STORE
}

// ---------------------------------------------------------------------------
// Kernel B (mma.sync, double-buffered): pool + fused sign-sqrt epilogue.
// D[128c x 32m] = (1/676) fm @ att^T; f -> out_fm (unnormalized); sum(f^2)
// atomicAdd'ed to g_ss[b]. CTAs with c0==0 also write the p bias row
// (replaces the k_scale launch; fc computes scales inline from g_ss).
// ---------------------------------------------------------------------------
#define CH       64
#define NCHUNK   11
#define A_HI_OFF 0
#define A_LO_OFF 16384
#define B_HI_OFF 32768
#define B_LO_OFF 36864
#define POOL_BUF 40960                  // 40*1024
#define POOL_SMEM_DYN (2 * POOL_BUF + 1024)

__global__ __launch_bounds__(256, 2) void k_pool_mma(
    const float* __restrict__ fmap, const float* __restrict__ att,
    float* __restrict__ out_fm, const float* __restrict__ fcb,
    float* __restrict__ out_p)
{
    extern __shared__ char dyn_smem[];

    const int b  = blockIdx.y;
    const int c0 = blockIdx.x * 128;
    const int t  = threadIdx.x;
    const int w  = t >> 5, lane = t & 31;
    const int rw = w * 16;

    uint32_t raw = smem_u32(dyn_smem);
    uint32_t abase = (raw + 1023u) & ~1023u;
    char* sbuf = dyn_smem + (abase - raw);

    const float* Aruns = fmap + (size_t)(b * Cc + c0) * HW;
    const float* Bruns = att  + (size_t)b * Mm * HW;

    float acc[4][4];
#pragma unroll
    for (int p = 0; p < 4; ++p)
#pragma unroll
        for (int j = 0; j < 4; ++j) acc[p][j] = 0.f;

    const int r8   = lane & 7;
    const int aRow = rw + ((lane >> 3) & 1) * 8 + r8;
    const int aColM = ((lane >> 4) & 1) * 16;
    const int bRow0 = ((lane >> 4) & 1) * 8 + r8;
    const int bColM = ((lane >> 3) & 1) * 16;

    float4 av[8], bv[2];
    const int arow[8] = { (t) >> 4, (t + 256) >> 4, (t + 512) >> 4, (t + 768) >> 4,
                          (t + 1024) >> 4, (t + 1280) >> 4, (t + 1536) >> 4, (t + 1792) >> 4 };
    const int aqc = t & 15;

#define POOL_LOAD(hw0_)                                                       \
    do {                                                                      \
        const int hwq_ = (hw0_) + aqc * 4;                                    \
        const bool ok_ = hwq_ + 3 < HW;                                       \
        _Pragma("unroll")                                                     \
        for (int i = 0; i < 8; ++i)                                           \
            av[i] = ok_ ? *(const float4*)(Aruns + (size_t)arow[i] * HW + hwq_) \
                        : make_float4(0.f, 0.f, 0.f, 0.f);                    \
        _Pragma("unroll")                                                     \
        for (int i = 0; i < 2; ++i) {                                         \
            int row_ = (t + i * 256) >> 4;                                    \
            bv[i] = ok_ ? *(const float4*)(Bruns + (size_t)row_ * HW + hwq_)  \
                        : make_float4(0.f, 0.f, 0.f, 0.f);                    \
        }                                                                     \
    } while (0)

#define POOL_STORE(dst_)                                                      \
    do {                                                                      \
        char* db_ = (dst_);                                                   \
        _Pragma("unroll")                                                     \
        for (int i = 0; i < 8; ++i) {                                         \
            uint32_t h01, l01, h23, l23;                                      \
            split_pack(av[i].x, av[i].y, h01, l01);                           \
            split_pack(av[i].z, av[i].w, h23, l23);                           \
            uint32_t off = SWZ128((uint32_t)(arow[i] * 128 + aqc * 8));       \
            *(uint2*)(db_ + A_HI_OFF + off) = make_uint2(h01, h23);           \
            *(uint2*)(db_ + A_LO_OFF + off) = make_uint2(l01, l23);           \
        }                                                                     \
        _Pragma("unroll")                                                     \
        for (int i = 0; i < 2; ++i) {                                         \
            int row_ = (t + i * 256) >> 4;                                    \
            uint32_t h01, l01, h23, l23;                                      \
            split_pack(bv[i].x, bv[i].y, h01, l01);                           \
            split_pack(bv[i].z, bv[i].w, h23, l23);                           \
            uint32_t off = SWZ128((uint32_t)(row_ * 128 + aqc * 8));          \
            *(uint2*)(db_ + B_HI_OFF + off) = make_uint2(h01, h23);           \
            *(uint2*)(db_ + B_LO_OFF + off) = make_uint2(l01, l23);           \
        }                                                                     \
    } while (0)

    POOL_LOAD(0);
    POOL_STORE(sbuf);
    __syncthreads();

    for (int chunk = 0; chunk < NCHUNK; ++chunk) {
        const uint32_t abuf = abase + (uint32_t)(chunk & 1) * POOL_BUF;
        if (chunk + 1 < NCHUNK) POOL_LOAD((chunk + 1) * CH);

#pragma unroll
        for (int ks = 0; ks < 4; ++ks) {
            const uint32_t aOff = SWZ128((uint32_t)(aRow * 128 + ks * 32 + aColM));
            uint32_t ah[4], al[4];
            ldsm_x4(abuf + A_HI_OFF + aOff, ah);
            ldsm_x4(abuf + A_LO_OFF + aOff, al);
#pragma unroll
            for (int pp = 0; pp < 2; ++pp) {
                const uint32_t bOff =
                    SWZ128((uint32_t)((pp * 16 + bRow0) * 128 + ks * 32 + bColM));
                uint32_t bh[4], bl[4];
                ldsm_x4(abuf + B_HI_OFF + bOff, bh);   // NON-trans (K-major B)
                ldsm_x4(abuf + B_LO_OFF + bOff, bl);
                mma_bf16(acc[2 * pp],     ah, bh[0], bh[1]);
                mma_bf16(acc[2 * pp],     ah, bl[0], bl[1]);
                mma_bf16(acc[2 * pp],     al, bh[0], bh[1]);
                mma_bf16(acc[2 * pp + 1], ah, bh[2], bh[3]);
                mma_bf16(acc[2 * pp + 1], ah, bl[2], bl[3]);
                mma_bf16(acc[2 * pp + 1], al, bh[2], bh[3]);
            }
        }

        if (chunk + 1 < NCHUNK) POOL_STORE(sbuf + ((chunk + 1) & 1) * POOL_BUF);
        __syncthreads();
    }

    // ---- fused epilogue: sign-sqrt, write unnormalized f, reduce sum(f^2) ----
    const float inv = 1.f / (float)HW;
    const int crow = c0 + rw + (lane >> 2);
    float ssq = 0.f;
#pragma unroll
    for (int p = 0; p < 4; ++p) {
        const int n = p * 8 + (lane & 3) * 2;
#pragma unroll
        for (int j = 0; j < 4; ++j) {
            float x = acc[p][j] * inv;
            float f = (x == 0.f) ? 0.f : copysignf(sqrtf(fabsf(x) + 1e-12f), x);
            acc[p][j] = f;
            ssq += f * f;
        }
        out_fm[((size_t)b * Mm + n)     * Cc + crow]     = acc[p][0];
        out_fm[((size_t)b * Mm + n + 1) * Cc + crow]     = acc[p][1];
        out_fm[((size_t)b * Mm + n)     * Cc + crow + 8] = acc[p][2];
        out_fm[((size_t)b * Mm + n + 1) * Cc + crow + 8] = acc[p][3];
    }
    __shared__ float red[8];
#pragma unroll
    for (int o = 16; o; o >>= 1) ssq += __shfl_xor_sync(0xffffffffu, ssq, o);
    if (lane == 0) red[w] = ssq;
    __syncthreads();
    if (t < 8) {
        float s = red[t];
#pragma unroll
        for (int o = 4; o; o >>= 1) s += __shfl_xor_sync(0xffu, s, o);
        if (t == 0) atomicAdd(&g_ss[b], s);
    }

    // p bias init for this batch (replaces the k_scale kernel)
    if (blockIdx.x == 0 && t < NCLS)
        out_p[b * NCLS + t] = __ldg(&fcb[t]);
#undef POOL_LOAD
#undef POOL_STORE
}

// ---------------------------------------------------------------------------
// Kernel D (mma.sync, double-buffered, split-k 96):
// p[b,n] += sum_k (f_unnorm[b,k] * 100/||f_b||) * fcw[n,k]
// Scales computed inline from g_ss (complete: pool kernel retired).
// ---------------------------------------------------------------------------
#define FC_NSPLIT 96
#define FC_KS     (MC / FC_NSPLIT)      // 256
#define FC_NCH    (FC_KS / 64)          // 4
#define FA_HI 0
#define FA_LO 8192
#define FB_HI 16384
#define FB_LO 24576
#define FC_BUF 32768
#define FC_SMEM_DYN (2 * FC_BUF + 1024)

__global__ __launch_bounds__(256, 2) void k_fc_mma(
    const float* __restrict__ fmn, const float* __restrict__ fcw,
    float* __restrict__ out_p)
{
    extern __shared__ char dyn_smem[];
    const int k0 = blockIdx.x * FC_KS;
    const int n0 = blockIdx.y * 64;
    const int t  = threadIdx.x;
    const int w  = t >> 5, lane = t & 31;
    const int wm = w & 3, wn = w >> 2;

    uint32_t raw = smem_u32(dyn_smem);
    uint32_t abase = (raw + 1023u) & ~1023u;
    char* sbuf = dyn_smem + (abase - raw);

    float acc[4][4];
#pragma unroll
    for (int p = 0; p < 4; ++p)
#pragma unroll
        for (int j = 0; j < 4; ++j) acc[p][j] = 0.f;

    const int r8   = lane & 7;
    const int aRow = wm * 16 + ((lane >> 3) & 1) * 8 + r8;
    const int aColM = ((lane >> 4) & 1) * 16;
    const int bRow0 = wn * 32 + ((lane >> 4) & 1) * 8 + r8;
    const int bColM = ((lane >> 3) & 1) * 16;

    // staging coords; per-row scale 100/max(||f||,eps) computed inline
    const int srow = t >> 4, sqc = t & 15;        // +16 rows per i-step
    float4 avv[4], bvv[4];
    float sA[4];
#pragma unroll
    for (int i = 0; i < 4; ++i)
        sA[i] = 100.f / fmaxf(sqrtf(g_ss[(srow + i * 16) & 63]), 1e-12f);

#define FC_LOAD(kc_)                                                          \
    do {                                                                      \
        _Pragma("unroll")                                                     \
        for (int i = 0; i < 4; ++i) {                                         \
            int row = srow + i * 16;                                          \
            float4 v = *(const float4*)(fmn + (size_t)row * MC + (kc_) + sqc * 4); \
            v.x *= sA[i]; v.y *= sA[i]; v.z *= sA[i]; v.w *= sA[i];           \
            avv[i] = v;                                                       \
            int n = n0 + row;                                                 \
            bvv[i] = (n < NCLS)                                               \
                ? *(const float4*)(fcw + (size_t)n * MC + (kc_) + sqc * 4)    \
                : make_float4(0.f, 0.f, 0.f, 0.f);                            \
        }                                                                     \
    } while (0)

#define FC_STORE(dst_)                                                        \
    do {                                                                      \
        char* db_ = (dst_);                                                   \
        _Pragma("unroll")                                                     \
        for (int i = 0; i < 4; ++i) {                                         \
            int row = srow + i * 16;                                          \
            uint32_t off = SWZ128((uint32_t)(row * 128 + sqc * 8));           \
            uint32_t h01, l01, h23, l23;                                      \
            split_pack(avv[i].x, avv[i].y, h01, l01);                         \
            split_pack(avv[i].z, avv[i].w, h23, l23);                         \
            *(uint2*)(db_ + FA_HI + off) = make_uint2(h01, h23);              \
            *(uint2*)(db_ + FA_LO + off) = make_uint2(l01, l23);              \
            split_pack(bvv[i].x, bvv[i].y, h01, l01);                         \
            split_pack(bvv[i].z, bvv[i].w, h23, l23);                         \
            *(uint2*)(db_ + FB_HI + off) = make_uint2(h01, h23);              \
            *(uint2*)(db_ + FB_LO + off) = make_uint2(l01, l23);              \
        }                                                                     \
    } while (0)

    FC_LOAD(k0);
    FC_STORE(sbuf);
    __syncthreads();

    for (int ch = 0; ch < FC_NCH; ++ch) {
        const uint32_t abuf = abase + (uint32_t)(ch & 1) * FC_BUF;
        if (ch + 1 < FC_NCH) FC_LOAD(k0 + (ch + 1) * 64);

#pragma unroll
        for (int ks = 0; ks < 4; ++ks) {
            const uint32_t aOff = SWZ128((uint32_t)(aRow * 128 + ks * 32 + aColM));
            uint32_t ah[4], al[4];
            ldsm_x4(abuf + FA_HI + aOff, ah);
            ldsm_x4(abuf + FA_LO + aOff, al);
#pragma unroll
            for (int pp = 0; pp < 2; ++pp) {
                const uint32_t bOff =
                    SWZ128((uint32_t)((bRow0 + pp * 16) * 128 + ks * 32 + bColM));
                uint32_t bh[4], bl[4];
                ldsm_x4(abuf + FB_HI + bOff, bh);
                ldsm_x4(abuf + FB_LO + bOff, bl);
                mma_bf16(acc[2 * pp],     ah, bh[0], bh[1]);
                mma_bf16(acc[2 * pp],     ah, bl[0], bl[1]);
                mma_bf16(acc[2 * pp],     al, bh[0], bh[1]);
                mma_bf16(acc[2 * pp + 1], ah, bh[2], bh[3]);
                mma_bf16(acc[2 * pp + 1], ah, bl[2], bl[3]);
                mma_bf16(acc[2 * pp + 1], al, bh[2], bh[3]);
            }
        }

        if (ch + 1 < FC_NCH) FC_STORE(sbuf + ((ch + 1) & 1) * FC_BUF);
        __syncthreads();
    }

    // epilogue: p[b, n] += acc (scale folded into A staging; bias from pool)
    const int brow = wm * 16 + (lane >> 2);
#pragma unroll
    for (int p = 0; p < 4; ++p) {
        const int n = n0 + wn * 32 + p * 8 + (lane & 3) * 2;
        if (n < NCLS) {
            atomicAdd(&out_p[brow * NCLS + n],       acc[p][0]);
            atomicAdd(&out_p[(brow + 8) * NCLS + n], acc[p][2]);
        }
        if (n + 1 < NCLS) {
            atomicAdd(&out_p[brow * NCLS + n + 1],       acc[p][1]);
            atomicAdd(&out_p[(brow + 8) * NCLS + n + 1], acc[p][3]);
        }
    }
#undef FC_LOAD
#undef FC_STORE
}

// ---------------------------------------------------------------------------
// Kernel E: normalize fm in place, float4-vectorized; scale from g_ss inline.
// ---------------------------------------------------------------------------
__global__ __launch_bounds__(256) void k_norm(float* __restrict__ out_fm)
{
    const int b = blockIdx.y;
    const float s = 1.f / fmaxf(sqrtf(g_ss[b]), 1e-12f);
    float4* p = (float4*)(out_fm + (size_t)b * MC) + blockIdx.x * 256 + threadIdx.x;
    float4 v = *p;
    v.x *= s; v.y *= s; v.z *= s; v.w *= s;
    *p = v;
}

// ---------------------------------------------------------------------------
extern "C" void kernel_launch(void* const* d_in, const int* in_sizes, int n_in,
                              void* d_out, int out_size)
{
    const float* fmap = (const float*)d_in[0];
    const float* attw = (const float*)d_in[1];
    const float* attb = (const float*)d_in[2];
    const float* fcw  = (const float*)d_in[3];
    const float* fcb  = (const float*)d_in[4];
    float* out     = (float*)d_out;
    float* out_p   = out + OFF_P;
    float* out_fm  = out + OFF_FM;
    float* out_att = out + OFF_ATT;
    (void)in_sizes; (void)n_in; (void)out_size;

    // >48KB dynamic smem opt-in (attribute set, not an allocation; idempotent)
    cudaFuncSetAttribute(k_att_mma,  cudaFuncAttributeMaxDynamicSharedMemorySize,
                         ATT_SMEM_DYN);
    cudaFuncSetAttribute(k_pool_mma, cudaFuncAttributeMaxDynamicSharedMemorySize,
                         POOL_SMEM_DYN);
    cudaFuncSetAttribute(k_fc_mma,   cudaFuncAttributeMaxDynamicSharedMemorySize,
                         FC_SMEM_DYN);

    // 4 launches (k_scale eliminated).
    k_att_mma <<<dim3(6, 64), 256, ATT_SMEM_DYN>>>(fmap, attw, attb, out_att);
    k_pool_mma<<<dim3(6, 64), 256, POOL_SMEM_DYN>>>(fmap, out_att, out_fm,
                                                    fcb, out_p);
    k_fc_mma  <<<dim3(FC_NSPLIT, 4), 256, FC_SMEM_DYN>>>(out_fm, fcw, out_p);
    k_norm    <<<dim3(24, 64), 256>>>(out_fm);
}

// round 17
// speedup vs baseline: 1.3095x; 1.3095x over previous
#include <cuda_runtime.h>
#include <cuda_bf16.h>
#include <cstdint>

// Problem constants
#define Bn   64
#define Cc   768
#define HW   676          // 26*26
#define Mm   32
#define NCLS 200
#define MC   (Mm*Cc)      // 24576
#define OFF_P   0
#define OFF_FM  (Bn*NCLS)                  // 12800
#define OFF_ATT (OFF_FM + Bn*MC)           // 12800 + 1572864

// Scratch (device-code use only; never passed from host).
__device__ float g_ss[Bn];             // per-batch sum of f^2 (atomic)
__device__ float g_scale[Bn];          // 1/max(||f||,eps)
__device__ float g_scale100[Bn];       // 100/max(||f||,eps)

// ===========================================================================
// Baseline-ISA tensor helpers (ldmatrix + mma.sync assemble for plain sm_103;
// tcgen05 does NOT — harness assembles a non-'a' target).
// ===========================================================================
__device__ __forceinline__ uint32_t smem_u32(const void* p) {
    uint32_t r;
    asm("{ .reg .u64 t; cvta.to.shared.u64 t, %1; cvt.u32.u64 %0, t; }"
        : "=r"(r) : "l"(p));
    return r;
}
#define SWZ128(o)  ((o) ^ (((o) >> 3) & 0x70))

__device__ __forceinline__ void ldsm_x4(uint32_t addr, uint32_t r[4]) {
    asm volatile("ldmatrix.sync.aligned.m8n8.x4.shared.b16 {%0,%1,%2,%3}, [%4];"
                 : "=r"(r[0]), "=r"(r[1]), "=r"(r[2]), "=r"(r[3]) : "r"(addr));
}
__device__ __forceinline__ void ldsm_x4_t(uint32_t addr, uint32_t r[4]) {
    asm volatile("ldmatrix.sync.aligned.m8n8.x4.trans.shared.b16 {%0,%1,%2,%3}, [%4];"
                 : "=r"(r[0]), "=r"(r[1]), "=r"(r[2]), "=r"(r[3]) : "r"(addr));
}
__device__ __forceinline__ void mma_bf16(float* c, const uint32_t a[4],
                                         uint32_t b0, uint32_t b1) {
    asm volatile(
        "mma.sync.aligned.m16n8k16.row.col.f32.bf16.bf16.f32 "
        "{%0,%1,%2,%3}, {%4,%5,%6,%7}, {%8,%9}, {%0,%1,%2,%3};"
        : "+f"(c[0]), "+f"(c[1]), "+f"(c[2]), "+f"(c[3])
        : "r"(a[0]), "r"(a[1]), "r"(a[2]), "r"(a[3]), "r"(b0), "r"(b1));
}

// hi/lo bf16 split of a float pair (exact residual; minimal issue count)
__device__ __forceinline__ void split_pack(float x, float y,
                                           uint32_t& hi, uint32_t& lo) {
    __nv_bfloat162 h2 = __floats2bfloat162_rn(x, y);    // x -> low half
    uint32_t h = *(uint32_t*)&h2;
    float hx = __uint_as_float(h << 16);
    float hy = __uint_as_float(h & 0xFFFF0000u);
    __nv_bfloat162 l2 = __floats2bfloat162_rn(x - hx, y - hy);
    hi = h;
    lo = *(uint32_t*)&l2;
}

// ---------------------------------------------------------------------------
// Kernel A (mma.sync, double-buffered): att = relu(W @ X + bias)
// Per CTA (hw-tile 128, batch b): D[32m x 128hw], K = c in 12 chunks of 64.
// EXACT R14 body (best measured). Also zeroes g_ss[b].
// ---------------------------------------------------------------------------
#define KCH      64
#define NKCH     12
#define PXB      272                    // X row pitch bytes (136 bf16)
#define X_HI_OFF 0                      // 64*272 = 17408
#define X_LO_OFF 17408
#define W_HI_OFF 34816                  // 34*1024 (SW128 region 1024-aligned)
#define W_LO_OFF 38912
#define ATT_BUF  43008                  // 42*1024
#define ATT_SMEM_DYN (2 * ATT_BUF + 1024)

__global__ __launch_bounds__(256, 2) void k_att_mma(
    const float* __restrict__ fmap, const float* __restrict__ attw,
    const float* __restrict__ attb, float* __restrict__ out_att)
{
    extern __shared__ char dyn_smem[];
    const int b   = blockIdx.y;
    const int hwt = blockIdx.x * 128;
    const int t   = threadIdx.x;
    const int w   = t >> 5, lane = t & 31;

    if (blockIdx.x == 0 && t == 0) g_ss[b] = 0.f;   // pre-zero for pool atomics

    uint32_t raw = smem_u32(dyn_smem);
    uint32_t abase = (raw + 1023u) & ~1023u;
    char* sbuf = dyn_smem + (abase - raw);

    const float* X = fmap + (size_t)b * Cc * HW;

    float acc[2][2][4];
#pragma unroll
    for (int mt = 0; mt < 2; ++mt)
#pragma unroll
        for (int nt = 0; nt < 2; ++nt)
#pragma unroll
            for (int j = 0; j < 4; ++j) acc[mt][nt][j] = 0.f;

    const int r8 = lane & 7;
    const int aRowIn = ((lane >> 3) & 1) * 8 + r8;
    const int aColB  = ((lane >> 4) & 1) * 16;
    const int bKrow  = lane & 15;
    const int bNcol  = w * 16 + ((lane >> 4) & 1) * 8;

    float4 xv[8], wv[2];
    const int xrow[8] = { (t) >> 5, (t + 256) >> 5, (t + 512) >> 5, (t + 768) >> 5,
                          (t + 1024) >> 5, (t + 1280) >> 5, (t + 1536) >> 5, (t + 1792) >> 5 };
    const int xqc  = t & 31;
    const int xhw  = hwt + xqc * 4;
    const bool xok = xhw < HW;          // HW%4==0 -> whole quad in range
    const int wrow[2] = { t >> 4, (t + 256) >> 4 };
    const int wqc  = t & 15;

#define ATT_LOAD(c0_)                                                         \
    do {                                                                      \
        _Pragma("unroll")                                                     \
        for (int i = 0; i < 8; ++i)                                           \
            xv[i] = xok ? *(const float4*)(X + (size_t)((c0_) + xrow[i]) * HW + xhw) \
                        : make_float4(0.f, 0.f, 0.f, 0.f);                    \
        _Pragma("unroll")                                                     \
        for (int i = 0; i < 2; ++i)                                           \
            wv[i] = *(const float4*)(attw + (size_t)wrow[i] * Cc + (c0_) + wqc * 4); \
    } while (0)

#define ATT_STORE(dst_)                                                       \
    do {                                                                      \
        char* db_ = (dst_);                                                   \
        _Pragma("unroll")                                                     \
        for (int i = 0; i < 8; ++i) {                                         \
            uint32_t h01, l01, h23, l23;                                      \
            split_pack(xv[i].x, xv[i].y, h01, l01);                           \
            split_pack(xv[i].z, xv[i].w, h23, l23);                           \
            uint32_t off = (uint32_t)(xrow[i] * PXB + xqc * 8);               \
            *(uint2*)(db_ + X_HI_OFF + off) = make_uint2(h01, h23);           \
            *(uint2*)(db_ + X_LO_OFF + off) = make_uint2(l01, l23);           \
        }                                                                     \
        _Pragma("unroll")                                                     \
        for (int i = 0; i < 2; ++i) {                                         \
            uint32_t h01, l01, h23, l23;                                      \
            split_pack(wv[i].x, wv[i].y, h01, l01);                           \
            split_pack(wv[i].z, wv[i].w, h23, l23);                           \
            uint32_t off = SWZ128((uint32_t)(wrow[i] * 128 + wqc * 8));       \
            *(uint2*)(db_ + W_HI_OFF + off) = make_uint2(h01, h23);           \
            *(uint2*)(db_ + W_LO_OFF + off) = make_uint2(l01, l23);           \
        }                                                                     \
    } while (0)

    ATT_LOAD(0);
    ATT_STORE(sbuf);
    __syncthreads();

    for (int ch = 0; ch < NKCH; ++ch) {
        const uint32_t abuf = abase + (uint32_t)(ch & 1) * ATT_BUF;
        if (ch + 1 < NKCH) ATT_LOAD((ch + 1) * KCH);   // LDG in flight over mma

#pragma unroll
        for (int ks = 0; ks < 4; ++ks) {
            uint32_t ah[2][4], al[2][4];
#pragma unroll
            for (int mt = 0; mt < 2; ++mt) {
                uint32_t aOff = SWZ128((uint32_t)((mt * 16 + aRowIn) * 128 +
                                                  ks * 32 + aColB));
                ldsm_x4(abuf + W_HI_OFF + aOff, ah[mt]);
                ldsm_x4(abuf + W_LO_OFF + aOff, al[mt]);
            }
            uint32_t bOff = (uint32_t)((ks * 16 + bKrow) * PXB + bNcol * 2);
            uint32_t bh[4], bl[4];
            ldsm_x4_t(abuf + X_HI_OFF + bOff, bh);
            ldsm_x4_t(abuf + X_LO_OFF + bOff, bl);
#pragma unroll
            for (int mt = 0; mt < 2; ++mt)
#pragma unroll
                for (int nt = 0; nt < 2; ++nt) {
                    mma_bf16(acc[mt][nt], ah[mt], bh[2 * nt], bh[2 * nt + 1]);
                    mma_bf16(acc[mt][nt], ah[mt], bl[2 * nt], bl[2 * nt + 1]);
                    mma_bf16(acc[mt][nt], al[mt], bh[2 * nt], bh[2 * nt + 1]);
                }
        }

        if (ch + 1 < NKCH) ATT_STORE(sbuf + ((ch + 1) & 1) * ATT_BUF);
        __syncthreads();
    }

    float* ob = out_att + (size_t)b * Mm * HW;
#pragma unroll
    for (int mt = 0; mt < 2; ++mt) {
        const int m  = mt * 16 + (lane >> 2);
        const float bs0 = __ldg(&attb[m]);
        const float bs8 = __ldg(&attb[m + 8]);
#pragma unroll
        for (int nt = 0; nt < 2; ++nt) {
            int hwc = hwt + w * 16 + nt * 8 + 2 * (lane & 3);
            if (hwc + 1 < HW) {
                ob[(size_t)m * HW + hwc]           = fmaxf(acc[mt][nt][0] + bs0, 0.f);
                ob[(size_t)m * HW + hwc + 1]       = fmaxf(acc[mt][nt][1] + bs0, 0.f);
                ob[(size_t)(m + 8) * HW + hwc]     = fmaxf(acc[mt][nt][2] + bs8, 0.f);
                ob[(size_t)(m + 8) * HW + hwc + 1] = fmaxf(acc[mt][nt][3] + bs8, 0.f);
            }
        }
    }
#undef ATT_LOAD
#undef ATT_STORE
}

// ---------------------------------------------------------------------------
// Kernel B (mma.sync, double-buffered): pool + fused sign-sqrt epilogue.
// EXACT R14 body — NO extra kernel args (pool is at the 128-reg cap; the R16
// bias-write addition caused mainloop spills and a 35us regression).
// ---------------------------------------------------------------------------
#define CH       64
#define NCHUNK   11
#define A_HI_OFF 0
#define A_LO_OFF 16384
#define B_HI_OFF 32768
#define B_LO_OFF 36864
#define POOL_BUF 40960                  // 40*1024
#define POOL_SMEM_DYN (2 * POOL_BUF + 1024)

__global__ __launch_bounds__(256, 2) void k_pool_mma(
    const float* __restrict__ fmap, const float* __restrict__ att,
    float* __restrict__ out_fm)
{
    extern __shared__ char dyn_smem[];

    const int b  = blockIdx.y;
    const int c0 = blockIdx.x * 128;
    const int t  = threadIdx.x;
    const int w  = t >> 5, lane = t & 31;
    const int rw = w * 16;

    uint32_t raw = smem_u32(dyn_smem);
    uint32_t abase = (raw + 1023u) & ~1023u;
    char* sbuf = dyn_smem + (abase - raw);

    const float* Aruns = fmap + (size_t)(b * Cc + c0) * HW;
    const float* Bruns = att  + (size_t)b * Mm * HW;

    float acc[4][4];
#pragma unroll
    for (int p = 0; p < 4; ++p)
#pragma unroll
        for (int j = 0; j < 4; ++j) acc[p][j] = 0.f;

    const int r8   = lane & 7;
    const int aRow = rw + ((lane >> 3) & 1) * 8 + r8;
    const int aColM = ((lane >> 4) & 1) * 16;
    const int bRow0 = ((lane >> 4) & 1) * 8 + r8;
    const int bColM = ((lane >> 3) & 1) * 16;

    float4 av[8], bv[2];
    const int arow[8] = { (t) >> 4, (t + 256) >> 4, (t + 512) >> 4, (t + 768) >> 4,
                          (t + 1024) >> 4, (t + 1280) >> 4, (t + 1536) >> 4, (t + 1792) >> 4 };
    const int aqc = t & 15;

#define POOL_LOAD(hw0_)                                                       \
    do {                                                                      \
        const int hwq_ = (hw0_) + aqc * 4;                                    \
        const bool ok_ = hwq_ + 3 < HW;                                       \
        _Pragma("unroll")                                                     \
        for (int i = 0; i < 8; ++i)                                           \
            av[i] = ok_ ? *(const float4*)(Aruns + (size_t)arow[i] * HW + hwq_) \
                        : make_float4(0.f, 0.f, 0.f, 0.f);                    \
        _Pragma("unroll")                                                     \
        for (int i = 0; i < 2; ++i) {                                         \
            int row_ = (t + i * 256) >> 4;                                    \
            bv[i] = ok_ ? *(const float4*)(Bruns + (size_t)row_ * HW + hwq_)  \
                        : make_float4(0.f, 0.f, 0.f, 0.f);                    \
        }                                                                     \
    } while (0)

#define POOL_STORE(dst_)                                                      \
    do {                                                                      \
        char* db_ = (dst_);                                                   \
        _Pragma("unroll")                                                     \
        for (int i = 0; i < 8; ++i) {                                         \
            uint32_t h01, l01, h23, l23;                                      \
            split_pack(av[i].x, av[i].y, h01, l01);                           \
            split_pack(av[i].z, av[i].w, h23, l23);                           \
            uint32_t off = SWZ128((uint32_t)(arow[i] * 128 + aqc * 8));       \
            *(uint2*)(db_ + A_HI_OFF + off) = make_uint2(h01, h23);           \
            *(uint2*)(db_ + A_LO_OFF + off) = make_uint2(l01, l23);           \
        }                                                                     \
        _Pragma("unroll")                                                     \
        for (int i = 0; i < 2; ++i) {                                         \
            int row_ = (t + i * 256) >> 4;                                    \
            uint32_t h01, l01, h23, l23;                                      \
            split_pack(bv[i].x, bv[i].y, h01, l01);                           \
            split_pack(bv[i].z, bv[i].w, h23, l23);                           \
            uint32_t off = SWZ128((uint32_t)(row_ * 128 + aqc * 8));          \
            *(uint2*)(db_ + B_HI_OFF + off) = make_uint2(h01, h23);           \
            *(uint2*)(db_ + B_LO_OFF + off) = make_uint2(l01, l23);           \
        }                                                                     \
    } while (0)

    POOL_LOAD(0);
    POOL_STORE(sbuf);
    __syncthreads();

    for (int chunk = 0; chunk < NCHUNK; ++chunk) {
        const uint32_t abuf = abase + (uint32_t)(chunk & 1) * POOL_BUF;
        if (chunk + 1 < NCHUNK) POOL_LOAD((chunk + 1) * CH);

#pragma unroll
        for (int ks = 0; ks < 4; ++ks) {
            const uint32_t aOff = SWZ128((uint32_t)(aRow * 128 + ks * 32 + aColM));
            uint32_t ah[4], al[4];
            ldsm_x4(abuf + A_HI_OFF + aOff, ah);
            ldsm_x4(abuf + A_LO_OFF + aOff, al);
#pragma unroll
            for (int pp = 0; pp < 2; ++pp) {
                const uint32_t bOff =
                    SWZ128((uint32_t)((pp * 16 + bRow0) * 128 + ks * 32 + bColM));
                uint32_t bh[4], bl[4];
                ldsm_x4(abuf + B_HI_OFF + bOff, bh);   // NON-trans (K-major B)
                ldsm_x4(abuf + B_LO_OFF + bOff, bl);
                mma_bf16(acc[2 * pp],     ah, bh[0], bh[1]);
                mma_bf16(acc[2 * pp],     ah, bl[0], bl[1]);
                mma_bf16(acc[2 * pp],     al, bh[0], bh[1]);
                mma_bf16(acc[2 * pp + 1], ah, bh[2], bh[3]);
                mma_bf16(acc[2 * pp + 1], ah, bl[2], bl[3]);
                mma_bf16(acc[2 * pp + 1], al, bh[2], bh[3]);
            }
        }

        if (chunk + 1 < NCHUNK) POOL_STORE(sbuf + ((chunk + 1) & 1) * POOL_BUF);
        __syncthreads();
    }

    // ---- fused epilogue: sign-sqrt, write unnormalized f, reduce sum(f^2) ----
    const float inv = 1.f / (float)HW;
    const int crow = c0 + rw + (lane >> 2);
    float ssq = 0.f;
#pragma unroll
    for (int p = 0; p < 4; ++p) {
        const int n = p * 8 + (lane & 3) * 2;
#pragma unroll
        for (int j = 0; j < 4; ++j) {
            float x = acc[p][j] * inv;
            float f = (x == 0.f) ? 0.f : copysignf(sqrtf(fabsf(x) + 1e-12f), x);
            acc[p][j] = f;
            ssq += f * f;
        }
        out_fm[((size_t)b * Mm + n)     * Cc + crow]     = acc[p][0];
        out_fm[((size_t)b * Mm + n + 1) * Cc + crow]     = acc[p][1];
        out_fm[((size_t)b * Mm + n)     * Cc + crow + 8] = acc[p][2];
        out_fm[((size_t)b * Mm + n + 1) * Cc + crow + 8] = acc[p][3];
    }
    __shared__ float red[8];
#pragma unroll
    for (int o = 16; o; o >>= 1) ssq += __shfl_xor_sync(0xffffffffu, ssq, o);
    if (lane == 0) red[w] = ssq;
    __syncthreads();
    if (t < 8) {
        float s = red[t];
#pragma unroll
        for (int o = 4; o; o >>= 1) s += __shfl_xor_sync(0xffu, s, o);
        if (t == 0) atomicAdd(&g_ss[b], s);
    }
#undef POOL_LOAD
#undef POOL_STORE
}

// ---------------------------------------------------------------------------
// Kernel C: scales from g_ss (tiny: 1 block x 64; bias now folded into fc,
// p zeroed by cudaMemsetAsync).
// ---------------------------------------------------------------------------
__global__ void k_scale()
{
    if (threadIdx.x < Bn) {
        float s = 1.f / fmaxf(sqrtf(g_ss[threadIdx.x]), 1e-12f);
        g_scale[threadIdx.x] = s;
        g_scale100[threadIdx.x] = 100.f * s;
    }
}

// ---------------------------------------------------------------------------
// Kernel D (mma.sync, double-buffered, split-k 96): EXACT R14 body except the
// epilogue: k0==0 CTAs add the fc bias (p is zero-initialized via memset).
// ---------------------------------------------------------------------------
#define FC_NSPLIT 96
#define FC_KS     (MC / FC_NSPLIT)      // 256
#define FC_NCH    (FC_KS / 64)          // 4
#define FA_HI 0
#define FA_LO 8192
#define FB_HI 16384
#define FB_LO 24576
#define FC_BUF 32768
#define FC_SMEM_DYN (2 * FC_BUF + 1024)

__global__ __launch_bounds__(256, 2) void k_fc_mma(
    const float* __restrict__ fmn, const float* __restrict__ fcw,
    const float* __restrict__ fcb, float* __restrict__ out_p)
{
    extern __shared__ char dyn_smem[];
    const int k0 = blockIdx.x * FC_KS;
    const int n0 = blockIdx.y * 64;
    const int t  = threadIdx.x;
    const int w  = t >> 5, lane = t & 31;
    const int wm = w & 3, wn = w >> 2;

    uint32_t raw = smem_u32(dyn_smem);
    uint32_t abase = (raw + 1023u) & ~1023u;
    char* sbuf = dyn_smem + (abase - raw);

    float acc[4][4];
#pragma unroll
    for (int p = 0; p < 4; ++p)
#pragma unroll
        for (int j = 0; j < 4; ++j) acc[p][j] = 0.f;

    const int r8   = lane & 7;
    const int aRow = wm * 16 + ((lane >> 3) & 1) * 8 + r8;
    const int aColM = ((lane >> 4) & 1) * 16;
    const int bRow0 = wn * 32 + ((lane >> 4) & 1) * 8 + r8;
    const int bColM = ((lane >> 3) & 1) * 16;

    // staging coords
    const int srow = t >> 4, sqc = t & 15;        // +16 rows per i-step
    float4 avv[4], bvv[4];
    float sA[4];
#pragma unroll
    for (int i = 0; i < 4; ++i)
        sA[i] = g_scale100[(srow + i * 16) & 63];

#define FC_LOAD(kc_)                                                          \
    do {                                                                      \
        _Pragma("unroll")                                                     \
        for (int i = 0; i < 4; ++i) {                                         \
            int row = srow + i * 16;                                          \
            float4 v = *(const float4*)(fmn + (size_t)row * MC + (kc_) + sqc * 4); \
            v.x *= sA[i]; v.y *= sA[i]; v.z *= sA[i]; v.w *= sA[i];           \
            avv[i] = v;                                                       \
            int n = n0 + row;                                                 \
            bvv[i] = (n < NCLS)                                               \
                ? *(const float4*)(fcw + (size_t)n * MC + (kc_) + sqc * 4)    \
                : make_float4(0.f, 0.f, 0.f, 0.f);                            \
        }                                                                     \
    } while (0)

#define FC_STORE(dst_)                                                        \
    do {                                                                      \
        char* db_ = (dst_);                                                   \
        _Pragma("unroll")                                                     \
        for (int i = 0; i < 4; ++i) {                                         \
            int row = srow + i * 16;                                          \
            uint32_t off = SWZ128((uint32_t)(row * 128 + sqc * 8));           \
            uint32_t h01, l01, h23, l23;                                      \
            split_pack(avv[i].x, avv[i].y, h01, l01);                         \
            split_pack(avv[i].z, avv[i].w, h23, l23);                         \
            *(uint2*)(db_ + FA_HI + off) = make_uint2(h01, h23);              \
            *(uint2*)(db_ + FA_LO + off) = make_uint2(l01, l23);              \
            split_pack(bvv[i].x, bvv[i].y, h01, l01);                         \
            split_pack(bvv[i].z, bvv[i].w, h23, l23);                         \
            *(uint2*)(db_ + FB_HI + off) = make_uint2(h01, h23);              \
            *(uint2*)(db_ + FB_LO + off) = make_uint2(l01, l23);              \
        }                                                                     \
    } while (0)

    FC_LOAD(k0);
    FC_STORE(sbuf);
    __syncthreads();

    for (int ch = 0; ch < FC_NCH; ++ch) {
        const uint32_t abuf = abase + (uint32_t)(ch & 1) * FC_BUF;
        if (ch + 1 < FC_NCH) FC_LOAD(k0 + (ch + 1) * 64);

#pragma unroll
        for (int ks = 0; ks < 4; ++ks) {
            const uint32_t aOff = SWZ128((uint32_t)(aRow * 128 + ks * 32 + aColM));
            uint32_t ah[4], al[4];
            ldsm_x4(abuf + FA_HI + aOff, ah);
            ldsm_x4(abuf + FA_LO + aOff, al);
#pragma unroll
            for (int pp = 0; pp < 2; ++pp) {
                const uint32_t bOff =
                    SWZ128((uint32_t)((bRow0 + pp * 16) * 128 + ks * 32 + bColM));
                uint32_t bh[4], bl[4];
                ldsm_x4(abuf + FB_HI + bOff, bh);
                ldsm_x4(abuf + FB_LO + bOff, bl);
                mma_bf16(acc[2 * pp],     ah, bh[0], bh[1]);
                mma_bf16(acc[2 * pp],     ah, bl[0], bl[1]);
                mma_bf16(acc[2 * pp],     al, bh[0], bh[1]);
                mma_bf16(acc[2 * pp + 1], ah, bh[2], bh[3]);
                mma_bf16(acc[2 * pp + 1], ah, bl[2], bl[3]);
                mma_bf16(acc[2 * pp + 1], al, bh[2], bh[3]);
            }
        }

        if (ch + 1 < FC_NCH) FC_STORE(sbuf + ((ch + 1) & 1) * FC_BUF);
        __syncthreads();
    }

    // epilogue: p[b, n] += acc (+ bias once, from the k0==0 split)
    const bool addb = (blockIdx.x == 0);
    const int brow = wm * 16 + (lane >> 2);
#pragma unroll
    for (int p = 0; p < 4; ++p) {
        const int n = n0 + wn * 32 + p * 8 + (lane & 3) * 2;
        if (n < NCLS) {
            float bsn = addb ? __ldg(&fcb[n]) : 0.f;
            atomicAdd(&out_p[brow * NCLS + n],       acc[p][0] + bsn);
            atomicAdd(&out_p[(brow + 8) * NCLS + n], acc[p][2] + bsn);
        }
        if (n + 1 < NCLS) {
            float bsn1 = addb ? __ldg(&fcb[n + 1]) : 0.f;
            atomicAdd(&out_p[brow * NCLS + n + 1],       acc[p][1] + bsn1);
            atomicAdd(&out_p[(brow + 8) * NCLS + n + 1], acc[p][3] + bsn1);
        }
    }
#undef FC_LOAD
#undef FC_STORE
}

// ---------------------------------------------------------------------------
// Kernel E: normalize fm in place, float4-vectorized (R14 version: g_scale).
// ---------------------------------------------------------------------------
__global__ __launch_bounds__(256) void k_norm(float* __restrict__ out_fm)
{
    const int b = blockIdx.y;
    const float s = g_scale[b];
    float4* p = (float4*)(out_fm + (size_t)b * MC) + blockIdx.x * 256 + threadIdx.x;
    float4 v = *p;
    v.x *= s; v.y *= s; v.z *= s; v.w *= s;
    *p = v;
}

// ---------------------------------------------------------------------------
extern "C" void kernel_launch(void* const* d_in, const int* in_sizes, int n_in,
                              void* d_out, int out_size)
{
    const float* fmap = (const float*)d_in[0];
    const float* attw = (const float*)d_in[1];
    const float* attb = (const float*)d_in[2];
    const float* fcw  = (const float*)d_in[3];
    const float* fcb  = (const float*)d_in[4];
    float* out     = (float*)d_out;
    float* out_p   = out + OFF_P;
    float* out_fm  = out + OFF_FM;
    float* out_att = out + OFF_ATT;
    (void)in_sizes; (void)n_in; (void)out_size;

    // >48KB dynamic smem opt-in (attribute set, not an allocation; idempotent)
    cudaFuncSetAttribute(k_att_mma,  cudaFuncAttributeMaxDynamicSharedMemorySize,
                         ATT_SMEM_DYN);
    cudaFuncSetAttribute(k_pool_mma, cudaFuncAttributeMaxDynamicSharedMemorySize,
                         POOL_SMEM_DYN);
    cudaFuncSetAttribute(k_fc_mma,   cudaFuncAttributeMaxDynamicSharedMemorySize,
                         FC_SMEM_DYN);

    // p zero-init (graph-capturable memset node; bias folded into k_fc_mma)
    cudaMemsetAsync(out_p, 0, (size_t)Bn * NCLS * sizeof(float));

    k_att_mma <<<dim3(6, 64), 256, ATT_SMEM_DYN>>>(fmap, attw, attb, out_att);
    k_pool_mma<<<dim3(6, 64), 256, POOL_SMEM_DYN>>>(fmap, out_att, out_fm);
    k_scale   <<<1, 64>>>();
    k_fc_mma  <<<dim3(FC_NSPLIT, 4), 256, FC_SMEM_DYN>>>(out_fm, fcw, fcb, out_p);
    k_norm    <<<dim3(24, 64), 256>>>(out_fm);
}